// round 5
// baseline (speedup 1.0000x reference)
#include <cuda_runtime.h>
#include <math.h>

#define KDIM 64
#define DEG 32
#define N0_MAX 65536
#define WPB 2        // warps per block
#define NPW0 4       // nodes per warp, hop0
#define NPW1 2       // rows per warp, hop1

// hop-0 aggregate scratch: 65536 x 64 f32 = 16 MB (static __device__, no alloc)
__device__ float g_agg0[N0_MAX * KDIM];

// ---- cp.async helpers (16B, L1-bypass) ----
__device__ __forceinline__ void cp16(void* smem_dst, const void* gsrc) {
    unsigned d = (unsigned)__cvta_generic_to_shared(smem_dst);
    asm volatile("cp.async.cg.shared.global [%0], [%1], 16;" :: "r"(d), "l"(gsrc));
}
__device__ __forceinline__ void cp_commit() {
    asm volatile("cp.async.commit_group;" ::: "memory");
}
template <int N>
__device__ __forceinline__ void cp_wait_group() {
    asm volatile("cp.async.wait_group %0;" :: "n"(N) : "memory");
}

// reduce across a 16-lane half-warp (xor 8,4,2,1)
__device__ __forceinline__ float half_sum(float v) {
#pragma unroll
    for (int o = 8; o > 0; o >>= 1) v += __shfl_xor_sync(0xffffffffu, v, o);
    return v;
}

// renorm scale: min(1, 1/max(sqrt(ss), 1e-12)) == ss > 1 ? rsqrt(ss) : 1
__device__ __forceinline__ float renorm_scale(float ss) {
    return (ss > 1.0f) ? rsqrtf(ss) : 1.0f;
}

// ============================ hop 0 ============================
// Warp handles NPW0 consecutive nodes, double-buffered: while reducing node k
// out of smem, node k+1's 33 row-chunks are in flight via cp.async.
// Buffer: rows 0-31 = neighbors, row 32 = target.

__device__ __forceinline__ void hop0_prefetch(
    float4* buf, const float* __restrict__ entity_emb,
    const int* __restrict__ node_ids0, const int* __restrict__ nbr0,
    int node, int lane, int sub, int sl)
{
    const int myidx = __ldg(nbr0 + (size_t)node * DEG + lane);
#pragma unroll
    for (int i = 0; i < 16; i++) {
        const int row = i + (sub << 4);
        const int id  = __shfl_sync(0xffffffffu, myidx, row);
        cp16(&buf[row * 16 + sl], entity_emb + (size_t)id * KDIM + sl * 4);
    }
    if (sub == 0) {
        const int tid = __ldg(node_ids0 + node);
        cp16(&buf[32 * 16 + sl], entity_emb + (size_t)tid * KDIM + sl * 4);
    }
    cp_commit();
}

__device__ __forceinline__ void hop0_reduce(
    const float4* buf, int node, int sub, int sl)
{
    float4 s = make_float4(0.f, 0.f, 0.f, 0.f);
    float4 q = make_float4(0.f, 0.f, 0.f, 0.f);
#pragma unroll
    for (int i = 0; i < 16; i++) {
        const float4 e = buf[(i + (sub << 4)) * 16 + sl];
        const float ss = half_sum(e.x * e.x + e.y * e.y + e.z * e.z + e.w * e.w);
        const float sc = renorm_scale(ss);
        const float ex = e.x * sc, ey = e.y * sc, ez = e.z * sc, ew = e.w * sc;
        s.x += ex; s.y += ey; s.z += ez; s.w += ew;
        q.x += ex * ex; q.y += ey * ey; q.z += ez * ez; q.w += ew * ew;
    }
    s.x += __shfl_xor_sync(0xffffffffu, s.x, 16);
    s.y += __shfl_xor_sync(0xffffffffu, s.y, 16);
    s.z += __shfl_xor_sync(0xffffffffu, s.z, 16);
    s.w += __shfl_xor_sync(0xffffffffu, s.w, 16);
    q.x += __shfl_xor_sync(0xffffffffu, q.x, 16);
    q.y += __shfl_xor_sync(0xffffffffu, q.y, 16);
    q.z += __shfl_xor_sync(0xffffffffu, q.z, 16);
    q.w += __shfl_xor_sync(0xffffffffu, q.w, 16);

    const float4 t  = buf[32 * 16 + sl];
    const float tsc = renorm_scale(half_sum(t.x * t.x + t.y * t.y +
                                            t.z * t.z + t.w * t.w));
    if (sub == 0) {
        float4 o;
        o.x = s.x * s.x - q.x + t.x * tsc;
        o.y = s.y * s.y - q.y + t.y * tsc;
        o.z = s.z * s.z - q.z + t.z * tsc;
        o.w = s.w * s.w - q.w + t.w * tsc;
        *((float4*)(g_agg0 + (size_t)node * KDIM) + sl) = o;
    }
}

__global__ void __launch_bounds__(WPB * 32) hop0_kernel(
    const float* __restrict__ entity_emb,
    const int* __restrict__ node_ids0,
    const int* __restrict__ nbr0,
    int n0)
{
    __shared__ float4 tile[WPB][2][33 * 16];   // 2 x 33 rows x 256B per warp

    const int w     = threadIdx.x >> 5;
    const int lane  = threadIdx.x & 31;
    const int sub   = lane >> 4;
    const int sl    = lane & 15;
    const int base  = (blockIdx.x * WPB + w) * NPW0;
    if (base >= n0) return;

    hop0_prefetch(tile[w][0], entity_emb, node_ids0, nbr0, base, lane, sub, sl);

#pragma unroll
    for (int k = 0; k < NPW0; k++) {
        const int node = base + k;
        if (k + 1 < NPW0 && node + 1 < n0) {
            hop0_prefetch(tile[w][(k + 1) & 1], entity_emb, node_ids0, nbr0,
                          node + 1, lane, sub, sl);
            cp_wait_group<1>();
        } else {
            cp_wait_group<0>();
        }
        __syncwarp();
        if (node < n0) hop0_reduce(tile[w][k & 1], node, sub, sl);
        __syncwarp();   // buffer reuse safety before next prefetch overwrites
    }
}

// ============================ hop 1 ============================
// rows 0-31 = agg0 gathers, row 32 = item target, row 33 = user row.

__device__ __forceinline__ void hop1_prefetch(
    float4* buf,
    const float* __restrict__ entity_emb,
    const float* __restrict__ user_emb,
    const int* __restrict__ u,
    const int* __restrict__ item_ids,
    const int* __restrict__ nbr1_idx,
    int b, int lane, int sub, int sl)
{
    const int myidx = __ldg(nbr1_idx + (size_t)b * DEG + lane);
#pragma unroll
    for (int i = 0; i < 16; i++) {
        const int row = i + (sub << 4);
        const int id  = __shfl_sync(0xffffffffu, myidx, row);
        cp16(&buf[row * 16 + sl], g_agg0 + (size_t)id * KDIM + sl * 4);
    }
    if (sub == 0) {
        const int it  = __ldg(item_ids + b);
        const int uid = __ldg(u + b);
        cp16(&buf[32 * 16 + sl], entity_emb + (size_t)it * KDIM + sl * 4);
        cp16(&buf[33 * 16 + sl], user_emb + (size_t)uid * KDIM + sl * 4);
    }
    cp_commit();
}

__device__ __forceinline__ void hop1_reduce(
    const float4* buf, float* __restrict__ out, int b, int lane, int sub, int sl)
{
    float4 s = make_float4(0.f, 0.f, 0.f, 0.f);
    float4 q = make_float4(0.f, 0.f, 0.f, 0.f);
#pragma unroll
    for (int i = 0; i < 16; i++) {
        const float4 e = buf[(i + (sub << 4)) * 16 + sl];
        s.x += e.x; s.y += e.y; s.z += e.z; s.w += e.w;
        q.x += e.x * e.x; q.y += e.y * e.y;
        q.z += e.z * e.z; q.w += e.w * e.w;
    }
    s.x += __shfl_xor_sync(0xffffffffu, s.x, 16);
    s.y += __shfl_xor_sync(0xffffffffu, s.y, 16);
    s.z += __shfl_xor_sync(0xffffffffu, s.z, 16);
    s.w += __shfl_xor_sync(0xffffffffu, s.w, 16);
    q.x += __shfl_xor_sync(0xffffffffu, q.x, 16);
    q.y += __shfl_xor_sync(0xffffffffu, q.y, 16);
    q.z += __shfl_xor_sync(0xffffffffu, q.z, 16);
    q.w += __shfl_xor_sync(0xffffffffu, q.w, 16);

    const float4 t  = buf[32 * 16 + sl];
    const float tsc = renorm_scale(half_sum(t.x * t.x + t.y * t.y +
                                            t.z * t.z + t.w * t.w));
    float4 items;
    items.x = s.x * s.x - q.x + t.x * tsc;
    items.y = s.y * s.y - q.y + t.y * tsc;
    items.z = s.z * s.z - q.z + t.z * tsc;
    items.w = s.w * s.w - q.w + t.w * tsc;

    const float4 usr = buf[33 * 16 + sl];
    const float usc  = renorm_scale(half_sum(usr.x * usr.x + usr.y * usr.y +
                                             usr.z * usr.z + usr.w * usr.w));
    const float dot = half_sum((usr.x * items.x + usr.y * items.y +
                                usr.z * items.z + usr.w * items.w) * usc);
    if (lane == 0) out[b] = 1.0f / (1.0f + expf(-dot));
}

__global__ void __launch_bounds__(WPB * 32) hop1_kernel(
    const float* __restrict__ entity_emb,
    const float* __restrict__ user_emb,
    const int* __restrict__ u,
    const int* __restrict__ item_ids,
    const int* __restrict__ nbr1_idx,
    float* __restrict__ out,
    int B)
{
    __shared__ float4 tile[WPB][2][34 * 16];

    const int w    = threadIdx.x >> 5;
    const int lane = threadIdx.x & 31;
    const int sub  = lane >> 4;
    const int sl   = lane & 15;
    const int base = (blockIdx.x * WPB + w) * NPW1;
    if (base >= B) return;

    hop1_prefetch(tile[w][0], entity_emb, user_emb, u, item_ids, nbr1_idx,
                  base, lane, sub, sl);

#pragma unroll
    for (int k = 0; k < NPW1; k++) {
        const int b = base + k;
        if (k + 1 < NPW1 && b + 1 < B) {
            hop1_prefetch(tile[w][(k + 1) & 1], entity_emb, user_emb, u,
                          item_ids, nbr1_idx, b + 1, lane, sub, sl);
            cp_wait_group<1>();
        } else {
            cp_wait_group<0>();
        }
        __syncwarp();
        if (b < B) hop1_reduce(tile[w][k & 1], out, b, lane, sub, sl);
        __syncwarp();
    }
}

extern "C" void kernel_launch(void* const* d_in, const int* in_sizes, int n_in,
                              void* d_out, int out_size)
{
    const float* entity_emb = (const float*)d_in[0];
    const float* user_emb   = (const float*)d_in[1];
    // d_in[2..5] = Wa, ba, Wh, bh : dead code (softmax over singleton axis == 1)
    const int* u         = (const int*)d_in[6];
    const int* item_ids  = (const int*)d_in[7];
    const int* nbr1_idx  = (const int*)d_in[8];
    const int* node_ids0 = (const int*)d_in[9];
    const int* nbr0      = (const int*)d_in[10];

    const int B  = in_sizes[6];   // 2048
    const int n0 = in_sizes[9];   // 65536

    {
        const int nodes_per_block = WPB * NPW0;
        const int blocks = (n0 + nodes_per_block - 1) / nodes_per_block;
        hop0_kernel<<<blocks, WPB * 32>>>(entity_emb, node_ids0, nbr0, n0);
    }
    {
        const int rows_per_block = WPB * NPW1;
        const int blocks = (B + rows_per_block - 1) / rows_per_block;
        hop1_kernel<<<blocks, WPB * 32>>>(
            entity_emb, user_emb, u, item_ids, nbr1_idx, (float*)d_out, B);
    }
}

// round 7
// speedup vs baseline: 1.1384x; 1.1384x over previous
#include <cuda_runtime.h>
#include <math.h>

#define KDIM 64
#define DEG 32
#define N0_MAX 65536

// hop-0 aggregate scratch: 65536 x 64 f32 = 16 MB (static __device__, no alloc)
__device__ float g_agg0[N0_MAX * KDIM];

// reduce across a 16-lane half-warp (xor 8,4,2,1)
__device__ __forceinline__ float half_sum(float v) {
#pragma unroll
    for (int o = 8; o > 0; o >>= 1) v += __shfl_xor_sync(0xffffffffu, v, o);
    return v;
}

// renorm scale: min(1, 1/max(sqrt(ss), 1e-12)) == ss > 1 ? rsqrt(ss) : 1
__device__ __forceinline__ float renorm_scale(float ss) {
    return (ss > 1.0f) ? rsqrtf(ss) : 1.0f;
}

// L2 evict-last policy handle (createpolicy + cache_hint is the legal form
// for 16B loads on sm_100; bare .L2::evict_last needs 32B shapes)
__device__ __forceinline__ unsigned long long mk_policy_el() {
    unsigned long long pol;
    asm volatile("createpolicy.fractional.L2::evict_last.b64 %0, 1.0;" : "=l"(pol));
    return pol;
}
__device__ __forceinline__ float4 ldg_el(const float4* p, unsigned long long pol) {
    float4 v;
    asm volatile("ld.global.nc.L2::cache_hint.v4.f32 {%0,%1,%2,%3}, [%4], %5;"
                 : "=f"(v.x), "=f"(v.y), "=f"(v.z), "=f"(v.w)
                 : "l"(p), "l"(pol));
    return v;
}

// ============================ hop 0 ============================
// One warp per node (R3 layout, best measured hop0). Half-warp `sub` covers
// neighbors {16*sub+i}; lane sl owns dims [4sl,4sl+3]. All 16 rows prefetched
// into registers; entity-table gathers carry an evict_last L2 hint.
__global__ void __launch_bounds__(128) hop0_kernel(
    const float* __restrict__ entity_emb,
    const int* __restrict__ node_ids0,
    const int* __restrict__ nbr0,
    int n0)
{
    const int node = blockIdx.x * (blockDim.x >> 5) + (threadIdx.x >> 5);
    const int lane = threadIdx.x & 31;
    const int sub  = lane >> 4;
    const int sl   = lane & 15;
    if (node >= n0) return;

    const unsigned long long pol = mk_policy_el();

    const int myidx = __ldg(nbr0 + (size_t)node * DEG + lane);
    const int tid   = __ldg(node_ids0 + node);

    float4 e[16];
#pragma unroll
    for (int i = 0; i < 16; i++) {
        const int id = __shfl_sync(0xffffffffu, myidx, i + (sub << 4));
        e[i] = ldg_el((const float4*)(entity_emb + (size_t)id * KDIM) + sl, pol);
    }
    float4 t = ldg_el((const float4*)(entity_emb + (size_t)tid * KDIM) + sl, pol);

    float4 s = make_float4(0.f, 0.f, 0.f, 0.f);
    float4 q = make_float4(0.f, 0.f, 0.f, 0.f);
#pragma unroll
    for (int i = 0; i < 16; i++) {
        const float ss = half_sum(e[i].x * e[i].x + e[i].y * e[i].y +
                                  e[i].z * e[i].z + e[i].w * e[i].w);
        const float sc = renorm_scale(ss);
        const float ex = e[i].x * sc, ey = e[i].y * sc;
        const float ez = e[i].z * sc, ew = e[i].w * sc;
        s.x += ex; s.y += ey; s.z += ez; s.w += ew;
        q.x += ex * ex; q.y += ey * ey; q.z += ez * ez; q.w += ew * ew;
    }

    s.x += __shfl_xor_sync(0xffffffffu, s.x, 16);
    s.y += __shfl_xor_sync(0xffffffffu, s.y, 16);
    s.z += __shfl_xor_sync(0xffffffffu, s.z, 16);
    s.w += __shfl_xor_sync(0xffffffffu, s.w, 16);
    q.x += __shfl_xor_sync(0xffffffffu, q.x, 16);
    q.y += __shfl_xor_sync(0xffffffffu, q.y, 16);
    q.z += __shfl_xor_sync(0xffffffffu, q.z, 16);
    q.w += __shfl_xor_sync(0xffffffffu, q.w, 16);

    const float tsc = renorm_scale(half_sum(t.x * t.x + t.y * t.y +
                                            t.z * t.z + t.w * t.w));

    if (sub == 0) {
        float4 o;
        o.x = s.x * s.x - q.x + t.x * tsc;
        o.y = s.y * s.y - q.y + t.y * tsc;
        o.z = s.z * s.z - q.z + t.z * tsc;
        o.w = s.w * s.w - q.w + t.w * tsc;
        *((float4*)(g_agg0 + (size_t)node * KDIM) + sl) = o;
    }
}

// ============================ hop 1 ============================
// One BLOCK (128 thr, 4 warps) per batch row: warp w handles neighbors
// [8w, 8w+8). Within a warp, half-warp sub takes 4 of those 8 rows; lane sl
// owns dims [4sl,4sl+3]. Partials combined via smem. 2048 blocks -> 8192
// warps chip-wide: latency of the L2-resident gathers is hidden by TLP.
__global__ void __launch_bounds__(128) hop1_kernel(
    const float* __restrict__ entity_emb,
    const float* __restrict__ user_emb,
    const int* __restrict__ u,
    const int* __restrict__ item_ids,
    const int* __restrict__ nbr1_idx,
    float* __restrict__ out,
    int B)
{
    __shared__ float4 sm_s[4][16];
    __shared__ float4 sm_q[4][16];

    const int b    = blockIdx.x;
    const int w    = threadIdx.x >> 5;
    const int lane = threadIdx.x & 31;
    const int sub  = lane >> 4;
    const int sl   = lane & 15;
    if (b >= B) return;

    // lanes 0-7 hold this warp's 8 neighbor indices
    const int myidx = (lane < 8)
        ? __ldg(nbr1_idx + (size_t)b * DEG + w * 8 + lane) : 0;

    // prefetch this warp's 4-rows-per-half-warp from g_agg0
    float4 e[4];
#pragma unroll
    for (int i = 0; i < 4; i++) {
        const int id = __shfl_sync(0xffffffffu, myidx, (sub << 2) + i);
        e[i] = *((const float4*)(g_agg0 + (size_t)id * KDIM) + sl);
    }

    float4 s = make_float4(0.f, 0.f, 0.f, 0.f);
    float4 q = make_float4(0.f, 0.f, 0.f, 0.f);
#pragma unroll
    for (int i = 0; i < 4; i++) {
        s.x += e[i].x; s.y += e[i].y; s.z += e[i].z; s.w += e[i].w;
        q.x += e[i].x * e[i].x; q.y += e[i].y * e[i].y;
        q.z += e[i].z * e[i].z; q.w += e[i].w * e[i].w;
    }

    // combine the two half-warps
    s.x += __shfl_xor_sync(0xffffffffu, s.x, 16);
    s.y += __shfl_xor_sync(0xffffffffu, s.y, 16);
    s.z += __shfl_xor_sync(0xffffffffu, s.z, 16);
    s.w += __shfl_xor_sync(0xffffffffu, s.w, 16);
    q.x += __shfl_xor_sync(0xffffffffu, q.x, 16);
    q.y += __shfl_xor_sync(0xffffffffu, q.y, 16);
    q.z += __shfl_xor_sync(0xffffffffu, q.z, 16);
    q.w += __shfl_xor_sync(0xffffffffu, q.w, 16);

    if (sub == 0) { sm_s[w][sl] = s; sm_q[w][sl] = q; }
    __syncthreads();

    if (w == 0) {
        // warp 0 combines the 4 warp partials
        float4 S = sm_s[0][sl], Q = sm_q[0][sl];
#pragma unroll
        for (int j = 1; j < 4; j++) {
            const float4 a = sm_s[j][sl], c = sm_q[j][sl];
            S.x += a.x; S.y += a.y; S.z += a.z; S.w += a.w;
            Q.x += c.x; Q.y += c.y; Q.z += c.z; Q.w += c.w;
        }

        const int it  = __ldg(item_ids + b);
        const int uid = __ldg(u + b);
        float4 t   = __ldg((const float4*)(entity_emb + (size_t)it * KDIM) + sl);
        float4 usr = __ldg((const float4*)(user_emb + (size_t)uid * KDIM) + sl);

        const float tsc = renorm_scale(half_sum(t.x * t.x + t.y * t.y +
                                                t.z * t.z + t.w * t.w));
        float4 items;
        items.x = S.x * S.x - Q.x + t.x * tsc;
        items.y = S.y * S.y - Q.y + t.y * tsc;
        items.z = S.z * S.z - Q.z + t.z * tsc;
        items.w = S.w * S.w - Q.w + t.w * tsc;

        const float usc = renorm_scale(half_sum(usr.x * usr.x + usr.y * usr.y +
                                                usr.z * usr.z + usr.w * usr.w));
        const float dot = half_sum((usr.x * items.x + usr.y * items.y +
                                    usr.z * items.z + usr.w * items.w) * usc);
        if (lane == 0) out[b] = 1.0f / (1.0f + expf(-dot));
    }
}

extern "C" void kernel_launch(void* const* d_in, const int* in_sizes, int n_in,
                              void* d_out, int out_size)
{
    const float* entity_emb = (const float*)d_in[0];
    const float* user_emb   = (const float*)d_in[1];
    // d_in[2..5] = Wa, ba, Wh, bh : dead code (softmax over singleton axis == 1)
    const int* u         = (const int*)d_in[6];
    const int* item_ids  = (const int*)d_in[7];
    const int* nbr1_idx  = (const int*)d_in[8];
    const int* node_ids0 = (const int*)d_in[9];
    const int* nbr0      = (const int*)d_in[10];

    const int B  = in_sizes[6];   // 2048
    const int n0 = in_sizes[9];   // 65536

    // hop 0: one warp per node, 4 warps per block
    {
        const int wpb = 4;
        const int blocks = (n0 + wpb - 1) / wpb;
        hop0_kernel<<<blocks, wpb * 32>>>(entity_emb, node_ids0, nbr0, n0);
    }
    // hop 1: one block (4 warps) per batch row
    hop1_kernel<<<B, 128>>>(entity_emb, user_emb, u, item_ids, nbr1_idx,
                            (float*)d_out, B);
}

// round 8
// speedup vs baseline: 1.1540x; 1.0137x over previous
#include <cuda_runtime.h>
#include <math.h>

#define KDIM 64
#define DEG 32
#define N0_MAX 65536

// hop-0 aggregate scratch: 65536 x 64 f32 = 16 MB (static __device__, no alloc)
__device__ float g_agg0[N0_MAX * KDIM];

// reduce across a 16-lane half-warp (xor 8,4,2,1)
__device__ __forceinline__ float half_sum(float v) {
#pragma unroll
    for (int o = 8; o > 0; o >>= 1) v += __shfl_xor_sync(0xffffffffu, v, o);
    return v;
}

// renorm scale: min(1, 1/max(sqrt(ss), 1e-12)) == ss > 1 ? rsqrt(ss) : 1
__device__ __forceinline__ float renorm_scale(float ss) {
    return (ss > 1.0f) ? rsqrtf(ss) : 1.0f;
}

// evict-last policy handle + 16B store with L2 cache hint: keeps the 16 MB
// agg0 result resident in L2 against hop0's ~520 MB streaming gather traffic,
// so hop1's gathers become L2 hits instead of DRAM misses.
__device__ __forceinline__ unsigned long long mk_policy_el() {
    unsigned long long pol;
    asm volatile("createpolicy.fractional.L2::evict_last.b64 %0, 1.0;" : "=l"(pol));
    return pol;
}
__device__ __forceinline__ void stg_el(float4* p, float4 v, unsigned long long pol) {
    asm volatile("st.global.L2::cache_hint.v4.f32 [%0], {%1,%2,%3,%4}, %5;"
                 :: "l"(p), "f"(v.x), "f"(v.y), "f"(v.z), "f"(v.w), "l"(pol)
                 : "memory");
}

// ============================ hop 0 ============================
// One warp per node (R3 layout, best measured hop0). Half-warp `sub` covers
// neighbors {16*sub+i}; lane sl owns dims [4sl,4sl+3]. All 16 rows prefetched
// into registers (deep MLP); agg0 stored with evict_last.
__global__ void __launch_bounds__(128) hop0_kernel(
    const float* __restrict__ entity_emb,
    const int* __restrict__ node_ids0,
    const int* __restrict__ nbr0,
    int n0)
{
    const int node = blockIdx.x * (blockDim.x >> 5) + (threadIdx.x >> 5);
    const int lane = threadIdx.x & 31;
    const int sub  = lane >> 4;
    const int sl   = lane & 15;
    if (node >= n0) return;

    const int myidx = __ldg(nbr0 + (size_t)node * DEG + lane);
    const int tid   = __ldg(node_ids0 + node);

    float4 e[16];
#pragma unroll
    for (int i = 0; i < 16; i++) {
        const int id = __shfl_sync(0xffffffffu, myidx, i + (sub << 4));
        e[i] = __ldg((const float4*)(entity_emb + (size_t)id * KDIM) + sl);
    }
    float4 t = __ldg((const float4*)(entity_emb + (size_t)tid * KDIM) + sl);

    float4 s = make_float4(0.f, 0.f, 0.f, 0.f);
    float4 q = make_float4(0.f, 0.f, 0.f, 0.f);
#pragma unroll
    for (int i = 0; i < 16; i++) {
        const float ss = half_sum(e[i].x * e[i].x + e[i].y * e[i].y +
                                  e[i].z * e[i].z + e[i].w * e[i].w);
        const float sc = renorm_scale(ss);
        const float ex = e[i].x * sc, ey = e[i].y * sc;
        const float ez = e[i].z * sc, ew = e[i].w * sc;
        s.x += ex; s.y += ey; s.z += ez; s.w += ew;
        q.x += ex * ex; q.y += ey * ey; q.z += ez * ez; q.w += ew * ew;
    }

    s.x += __shfl_xor_sync(0xffffffffu, s.x, 16);
    s.y += __shfl_xor_sync(0xffffffffu, s.y, 16);
    s.z += __shfl_xor_sync(0xffffffffu, s.z, 16);
    s.w += __shfl_xor_sync(0xffffffffu, s.w, 16);
    q.x += __shfl_xor_sync(0xffffffffu, q.x, 16);
    q.y += __shfl_xor_sync(0xffffffffu, q.y, 16);
    q.z += __shfl_xor_sync(0xffffffffu, q.z, 16);
    q.w += __shfl_xor_sync(0xffffffffu, q.w, 16);

    const float tsc = renorm_scale(half_sum(t.x * t.x + t.y * t.y +
                                            t.z * t.z + t.w * t.w));

    if (sub == 0) {
        float4 o;
        o.x = s.x * s.x - q.x + t.x * tsc;
        o.y = s.y * s.y - q.y + t.y * tsc;
        o.z = s.z * s.z - q.z + t.z * tsc;
        o.w = s.w * s.w - q.w + t.w * tsc;
        const unsigned long long pol = mk_policy_el();
        stg_el((float4*)(g_agg0 + (size_t)node * KDIM) + sl, o, pol);
    }
}

// ============================ hop 1 ============================
// One BLOCK (128 thr, 4 warps) per batch row: warp w handles neighbors
// [8w, 8w+8). Within a warp, half-warp sub takes 4 of those 8 rows; lane sl
// owns dims [4sl,4sl+3]. Partials combined via smem.
__global__ void __launch_bounds__(128) hop1_kernel(
    const float* __restrict__ entity_emb,
    const float* __restrict__ user_emb,
    const int* __restrict__ u,
    const int* __restrict__ item_ids,
    const int* __restrict__ nbr1_idx,
    float* __restrict__ out,
    int B)
{
    __shared__ float4 sm_s[4][16];
    __shared__ float4 sm_q[4][16];

    const int b    = blockIdx.x;
    const int w    = threadIdx.x >> 5;
    const int lane = threadIdx.x & 31;
    const int sub  = lane >> 4;
    const int sl   = lane & 15;
    if (b >= B) return;

    // lanes 0-7 hold this warp's 8 neighbor indices
    const int myidx = (lane < 8)
        ? __ldg(nbr1_idx + (size_t)b * DEG + w * 8 + lane) : 0;

    float4 e[4];
#pragma unroll
    for (int i = 0; i < 4; i++) {
        const int id = __shfl_sync(0xffffffffu, myidx, (sub << 2) + i);
        e[i] = *((const float4*)(g_agg0 + (size_t)id * KDIM) + sl);
    }

    float4 s = make_float4(0.f, 0.f, 0.f, 0.f);
    float4 q = make_float4(0.f, 0.f, 0.f, 0.f);
#pragma unroll
    for (int i = 0; i < 4; i++) {
        s.x += e[i].x; s.y += e[i].y; s.z += e[i].z; s.w += e[i].w;
        q.x += e[i].x * e[i].x; q.y += e[i].y * e[i].y;
        q.z += e[i].z * e[i].z; q.w += e[i].w * e[i].w;
    }

    s.x += __shfl_xor_sync(0xffffffffu, s.x, 16);
    s.y += __shfl_xor_sync(0xffffffffu, s.y, 16);
    s.z += __shfl_xor_sync(0xffffffffu, s.z, 16);
    s.w += __shfl_xor_sync(0xffffffffu, s.w, 16);
    q.x += __shfl_xor_sync(0xffffffffu, q.x, 16);
    q.y += __shfl_xor_sync(0xffffffffu, q.y, 16);
    q.z += __shfl_xor_sync(0xffffffffu, q.z, 16);
    q.w += __shfl_xor_sync(0xffffffffu, q.w, 16);

    if (sub == 0) { sm_s[w][sl] = s; sm_q[w][sl] = q; }
    __syncthreads();

    if (w == 0) {
        float4 S = sm_s[0][sl], Q = sm_q[0][sl];
#pragma unroll
        for (int j = 1; j < 4; j++) {
            const float4 a = sm_s[j][sl], c = sm_q[j][sl];
            S.x += a.x; S.y += a.y; S.z += a.z; S.w += a.w;
            Q.x += c.x; Q.y += c.y; Q.z += c.z; Q.w += c.w;
        }

        const int it  = __ldg(item_ids + b);
        const int uid = __ldg(u + b);
        float4 t   = __ldg((const float4*)(entity_emb + (size_t)it * KDIM) + sl);
        float4 usr = __ldg((const float4*)(user_emb + (size_t)uid * KDIM) + sl);

        const float tsc = renorm_scale(half_sum(t.x * t.x + t.y * t.y +
                                                t.z * t.z + t.w * t.w));
        float4 items;
        items.x = S.x * S.x - Q.x + t.x * tsc;
        items.y = S.y * S.y - Q.y + t.y * tsc;
        items.z = S.z * S.z - Q.z + t.z * tsc;
        items.w = S.w * S.w - Q.w + t.w * tsc;

        const float usc = renorm_scale(half_sum(usr.x * usr.x + usr.y * usr.y +
                                                usr.z * usr.z + usr.w * usr.w));
        const float dot = half_sum((usr.x * items.x + usr.y * items.y +
                                    usr.z * items.z + usr.w * items.w) * usc);
        if (lane == 0) out[b] = 1.0f / (1.0f + expf(-dot));
    }
}

extern "C" void kernel_launch(void* const* d_in, const int* in_sizes, int n_in,
                              void* d_out, int out_size)
{
    const float* entity_emb = (const float*)d_in[0];
    const float* user_emb   = (const float*)d_in[1];
    // d_in[2..5] = Wa, ba, Wh, bh : dead code (softmax over singleton axis == 1)
    const int* u         = (const int*)d_in[6];
    const int* item_ids  = (const int*)d_in[7];
    const int* nbr1_idx  = (const int*)d_in[8];
    const int* node_ids0 = (const int*)d_in[9];
    const int* nbr0      = (const int*)d_in[10];

    const int B  = in_sizes[6];   // 2048
    const int n0 = in_sizes[9];   // 65536

    // hop 0: one warp per node, 4 warps per block
    {
        const int wpb = 4;
        const int blocks = (n0 + wpb - 1) / wpb;
        hop0_kernel<<<blocks, wpb * 32>>>(entity_emb, node_ids0, nbr0, n0);
    }
    // hop 1: one block (4 warps) per batch row
    hop1_kernel<<<B, 128>>>(entity_emb, user_emb, u, item_ids, nbr1_idx,
                            (float*)d_out, B);
}